// round 17
// baseline (speedup 1.0000x reference)
#include <cuda_runtime.h>

#define B_  32
#define T_  4
#define L_  256
#define D_  768
#define H_  12
#define DH_ 64
#define N_  (B_*T_*L_)   // 32768 rows

// ---------------- scratch (no allocations allowed) ----------------
__device__ float g_Hq[(size_t)N_*D_];
__device__ float g_Hk[(size_t)N_*D_];
__device__ float g_Hv[(size_t)N_*D_];
__device__ float g_O [(size_t)N_*D_];
__device__ float g_Y [(size_t)N_*D_];
__device__ unsigned long long g_Mq[(size_t)N_*H_];
__device__ unsigned long long g_Mk[(size_t)N_*H_];
__device__ unsigned long long g_Mv[(size_t)N_*H_];
__device__ unsigned g_cnt[256];   // completion counters: [z*64 + b*2 + half], final at 192+

// ---------------- packed f32x2 helpers (sm_103a) ----------------
__device__ __forceinline__ unsigned long long pack2(float lo, float hi) {
    unsigned long long r;
    asm("mov.b64 %0, {%1, %2};" : "=l"(r) : "f"(lo), "f"(hi));
    return r;
}
__device__ __forceinline__ void unpack2(unsigned long long v, float& lo, float& hi) {
    asm("mov.b64 {%0, %1}, %2;" : "=f"(lo), "=f"(hi) : "l"(v));
}
__device__ __forceinline__ unsigned long long ffma2(
    unsigned long long a, unsigned long long b, unsigned long long c) {
    unsigned long long d;
    asm("fma.rn.f32x2 %0, %1, %2, %3;" : "=l"(d) : "l"(a), "l"(b), "l"(c));
    return d;
}

// smem union: GEMM tiles (16KB) / LN row buffer (24KB)
#define AS(bf,kk,i) smem_u[(bf)*1024 + (kk)*128 + (i)]
#define BS(bf,kk,i) smem_u[2048 + (bf)*1024 + (kk)*128 + (i)]

// ====== GEMM (z-merged) + fused LN/LIF epilogue via completion counters ======
// GEMM: single ascending-k FMA chain per element — bitwise-exact. DO NOT reorder.
// LN: XLA:CPU NEON-VF8 reduce, exact op order — executed by the 24th (last)
// block of each (z,b,half) group, overlapping remaining GEMM work.
__global__ __launch_bounds__(256) void gemm_ln_kernel(
    const float* __restrict__ A,
    const float* __restrict__ W0, const float* __restrict__ W1, const float* __restrict__ W2,
    const float* __restrict__ b0, const float* __restrict__ b1, const float* __restrict__ b2,
    float* __restrict__ C0, float* __restrict__ C1, float* __restrict__ C2,
    const float* __restrict__ g0_, const float* __restrict__ g1_, const float* __restrict__ g2_,
    const float* __restrict__ e0_, const float* __restrict__ e1_, const float* __restrict__ e2_,
    unsigned long long* __restrict__ M0, unsigned long long* __restrict__ M1,
    unsigned long long* __restrict__ M2,
    float* __restrict__ S0, float* __restrict__ S1, float* __restrict__ S2,
    unsigned* __restrict__ cnt, int cntBase, float thr)
{
    const int z = blockIdx.z;
    const float* W    = (z == 0) ? W0 : (z == 1) ? W1 : W2;
    const float* bias = (z == 0) ? b0 : (z == 1) ? b1 : b2;
    float*       C    = (z == 0) ? C0 : (z == 1) ? C1 : C2;

    __shared__ __align__(16) float smem_u[6144];   // 24KB union
    __shared__ unsigned trig;
    const int tid  = threadIdx.x;
    const int tx   = tid & 15;
    const int ty   = tid >> 4;
    const int m0   = blockIdx.y * 128;
    const int n0   = blockIdx.x * 128;
    const int arow = tid >> 1;
    const int ak   = (tid & 1) * 4;

    const float* Aptr = A + (size_t)(m0 + arow) * 768 + ak;
    const float* Wptr = W + (size_t)(n0 + arow) * 768 + ak;

    unsigned long long acc2[8][4];
#pragma unroll
    for (int i = 0; i < 8; i++)
#pragma unroll
        for (int j = 0; j < 4; j++) acc2[i][j] = 0ULL;

    float4 av = *(const float4*)(Aptr);
    float4 wv = *(const float4*)(Wptr);
    AS(0, ak + 0, arow) = av.x; AS(0, ak + 1, arow) = av.y;
    AS(0, ak + 2, arow) = av.z; AS(0, ak + 3, arow) = av.w;
    BS(0, ak + 0, arow) = wv.x; BS(0, ak + 1, arow) = wv.y;
    BS(0, ak + 2, arow) = wv.z; BS(0, ak + 3, arow) = wv.w;
    __syncthreads();

    int buf = 0;
    for (int k0 = 0; k0 < 768; k0 += 8) {
        const bool more = (k0 + 8 < 768);
        if (more) {
            av = *(const float4*)(Aptr + k0 + 8);
            wv = *(const float4*)(Wptr + k0 + 8);
        }
#pragma unroll
        for (int kk = 0; kk < 8; kk++) {          // ascending k
            float a[8];
            *(float4*)&a[0] = *(const float4*)&AS(buf, kk, ty * 8 + 0);
            *(float4*)&a[4] = *(const float4*)&AS(buf, kk, ty * 8 + 4);
            const ulonglong2 b01 = *(const ulonglong2*)&BS(buf, kk, tx * 8 + 0);
            const ulonglong2 b23 = *(const ulonglong2*)&BS(buf, kk, tx * 8 + 4);
            unsigned long long b2[4];
            b2[0] = b01.x; b2[1] = b01.y; b2[2] = b23.x; b2[3] = b23.y;
#pragma unroll
            for (int i = 0; i < 8; i++) {
                const unsigned long long a2 = pack2(a[i], a[i]);
#pragma unroll
                for (int j = 0; j < 4; j++)
                    acc2[i][j] = ffma2(a2, b2[j], acc2[i][j]);
            }
        }
        if (more) {
            const int nb = buf ^ 1;
            AS(nb, ak + 0, arow) = av.x; AS(nb, ak + 1, arow) = av.y;
            AS(nb, ak + 2, arow) = av.z; AS(nb, ak + 3, arow) = av.w;
            BS(nb, ak + 0, arow) = wv.x; BS(nb, ak + 1, arow) = wv.y;
            BS(nb, ak + 2, arow) = wv.z; BS(nb, ak + 3, arow) = wv.w;
            __syncthreads();
            buf = nb;
        }
    }

#pragma unroll
    for (int i = 0; i < 8; i++) {
        float* cp = C + (size_t)(m0 + ty * 8 + i) * 768 + n0 + tx * 8;
#pragma unroll
        for (int j = 0; j < 4; j++) {
            float c0, c1;
            unpack2(acc2[i][j], c0, c1);
            cp[2 * j + 0] = __fadd_rn(c0, bias[n0 + tx * 8 + 2 * j + 0]);
            cp[2 * j + 1] = __fadd_rn(c1, bias[n0 + tx * 8 + 2 * j + 1]);
        }
    }

    // ---- completion-counter handshake ----
    __threadfence();
    const int bb   = blockIdx.y >> 3;          // batch
    const int half = blockIdx.y & 1;           // l-half (0:0..127, 1:128..255)
    if (tid == 0)
        trig = atomicAdd(&cnt[cntBase + z * 64 + bb * 2 + half], 1u);
    __syncthreads();                           // also retires all smem use
    if (trig != 23u) return;

    // ---- fused LN + LIF for group (z, bb, half): 128 rows x 4 t ----
    const float* gam = (z == 0) ? g0_ : (z == 1) ? g1_ : g2_;
    const float* bet = (z == 0) ? e0_ : (z == 1) ? e1_ : e2_;
    unsigned long long* Mout = (z == 0) ? M0 : (z == 1) ? M1 : M2;
    float* Sout = (z == 0) ? S0 : (z == 1) ? S1 : S2;
    float (*xs)[768] = (float(*)[768])smem_u;

    const int w = tid >> 5;
    const int j = tid & 31;

    for (int r = 0; r < 16; r++) {
        const int l = half * 128 + w * 16 + r;
        float v[24];
#pragma unroll
        for (int k = 0; k < 24; k++) v[k] = 0.0f;

        for (int t = 0; t < T_; t++) {
            const size_t row = (size_t)(bb * T_ + t) * L_ + l;
            const size_t off = row * D_;
#pragma unroll
            for (int k = 0; k < 24; k++)
                xs[w][j + 32 * k] = C[off + j + 32 * k];
            __syncwarp();

            // mean: 8-lane stride-8 serial partials (EXACT order)
            float p = 0.0f;
            if (j < 8) {
#pragma unroll 8
                for (int i = 0; i < 96; i++)
                    p = __fadd_rn(p, xs[w][8 * i + j]);
            }
            p = __fadd_rn(p, __shfl_xor_sync(0xffffffffu, p, 4));
            p = __fadd_rn(p, __shfl_xor_sync(0xffffffffu, p, 1));
            p = __fadd_rn(p, __shfl_xor_sync(0xffffffffu, p, 2));
            const float sum = __shfl_sync(0xffffffffu, p, 0);
            const float m = __fdiv_rn(sum, 768.0f);

            // variance (EXACT order)
            float q = 0.0f;
            if (j < 8) {
#pragma unroll 8
                for (int i = 0; i < 96; i++) {
                    const float d = __fsub_rn(xs[w][8 * i + j], m);
                    q = __fadd_rn(q, __fmul_rn(d, d));
                }
            }
            q = __fadd_rn(q, __shfl_xor_sync(0xffffffffu, q, 4));
            q = __fadd_rn(q, __shfl_xor_sync(0xffffffffu, q, 1));
            q = __fadd_rn(q, __shfl_xor_sync(0xffffffffu, q, 2));
            const float sum2 = __shfl_sync(0xffffffffu, q, 0);
            const float var = __fdiv_rn(sum2, 768.0f);
            const float rs  = __fsqrt_rn(__fadd_rn(var, 1e-5f));

            // normalize + LIF (EXACT op sequence)
            unsigned btmp = 0u;
#pragma unroll
            for (int k = 0; k < 24; k++) {
                const float x = xs[w][j + 32 * k];
                const float gk  = __ldg(&gam[j + 32 * k]);
                const float bek = __ldg(&bet[j + 32 * k]);
                const float d = __fsub_rn(x, m);
                const float h = __fadd_rn(__fmul_rn(__fdiv_rn(d, rs), gk), bek);
                v[k] = __fadd_rn(v[k], __fmul_rn(__fsub_rn(h, v[k]), 0.5f));
                const bool f = (__fsub_rn(v[k], thr) >= 0.0f);
                if (Sout) Sout[off + j + 32 * k] = f ? 1.0f : 0.0f;
                v[k] = f ? 0.0f : v[k];
                if (Mout) {
                    const unsigned bal = __ballot_sync(0xffffffffu, f);
                    if ((k & 1) == 0) btmp = bal;
                    else if (j == (k >> 1))
                        Mout[row * H_ + (k >> 1)] =
                            (unsigned long long)btmp | ((unsigned long long)bal << 32);
                }
            }
            __syncwarp();
        }
    }
}

// ===== attention: QK via mask popcount, AV via dp4a; V expanded from masks =====
__global__ __launch_bounds__(256) void attn_kernel(
    const unsigned long long* __restrict__ Mq, const unsigned long long* __restrict__ Mk,
    const unsigned long long* __restrict__ Mv, float* __restrict__ O)
{
    __shared__ unsigned long long Km[64];
    __shared__ unsigned long long Vm[64];
    __shared__ __align__(16) unsigned Vs8[64][16];
    const int h = blockIdx.x;
    const int t = blockIdx.y;
    const int b = blockIdx.z;
    const size_t rowbase = (size_t)(b * T_ + t) * L_;
    const int col = h * DH_;
    const int l = threadIdx.x;

    const unsigned long long qmask = Mq[(rowbase + l) * H_ + h];

    int o32[64];
#pragma unroll
    for (int d = 0; d < 64; d++) o32[d] = 0;

    for (int m0 = 0; m0 < L_; m0 += 64) {
        __syncthreads();
        if (threadIdx.x < 64)
            Km[threadIdx.x] = Mk[(rowbase + m0 + threadIdx.x) * H_ + h];
        else if (threadIdx.x < 128)
            Vm[threadIdx.x - 64] = Mv[(rowbase + m0 + threadIdx.x - 64) * H_ + h];
        __syncthreads();
        for (int wv = threadIdx.x; wv < 1024; wv += 256) {
            const int d  = wv >> 4;
            const int mg = wv & 15;
            const unsigned b0 = (unsigned)(Vm[4 * mg + 0] >> d) & 1u;
            const unsigned b1 = (unsigned)(Vm[4 * mg + 1] >> d) & 1u;
            const unsigned b2 = (unsigned)(Vm[4 * mg + 2] >> d) & 1u;
            const unsigned b3 = (unsigned)(Vm[4 * mg + 3] >> d) & 1u;
            Vs8[d][mg] = b0 | (b1 << 8) | (b2 << 16) | (b3 << 24);
        }
        __syncthreads();

#pragma unroll 1
        for (int mq = 0; mq < 4; mq++) {
            unsigned a4[4];
#pragma unroll
            for (int r = 0; r < 4; r++) {
                const int mg = mq * 4 + r;
                const int a0 = __popcll(qmask & Km[4 * mg + 0]);
                const int a1 = __popcll(qmask & Km[4 * mg + 1]);
                const int a2 = __popcll(qmask & Km[4 * mg + 2]);
                const int a3 = __popcll(qmask & Km[4 * mg + 3]);
                a4[r] = (unsigned)a0 | ((unsigned)a1 << 8) |
                        ((unsigned)a2 << 16) | ((unsigned)a3 << 24);
            }
#pragma unroll
            for (int d = 0; d < 64; d++) {
                const uint4 vv = *(const uint4*)&Vs8[d][mq * 4];
                int acc = o32[d];
                acc = __dp4a((int)a4[0], (int)vv.x, acc);
                acc = __dp4a((int)a4[1], (int)vv.y, acc);
                acc = __dp4a((int)a4[2], (int)vv.z, acc);
                acc = __dp4a((int)a4[3], (int)vv.w, acc);
                o32[d] = acc;
            }
        }
    }

    float* op = O + (rowbase + l) * D_ + col;
#pragma unroll
    for (int d = 0; d < 64; d += 4) {
        float4 v4;
        v4.x = __fmul_rn((float)o32[d + 0], 0.25f);
        v4.y = __fmul_rn((float)o32[d + 1], 0.25f);
        v4.z = __fmul_rn((float)o32[d + 2], 0.25f);
        v4.w = __fmul_rn((float)o32[d + 3], 0.25f);
        *(float4*)(op + d) = v4;
    }
}

// ========== LIF over T on O (thr = 0.5, exact dyadic), in place, float4 ==========
__global__ __launch_bounds__(256) void lif2_kernel(float4* __restrict__ IO)
{
    const int nq = (L_ * D_) / 4;
    const int idx = blockIdx.x * 256 + threadIdx.x;
    const int b = idx / nq;
    const int r = idx % nq;
    float4 v = make_float4(0.f, 0.f, 0.f, 0.f);
#pragma unroll
    for (int t = 0; t < T_; t++) {
        const size_t off = ((size_t)(b * T_ + t)) * (size_t)nq + r;
        float4 x = IO[off];
        v.x = __fadd_rn(v.x, __fmul_rn(__fsub_rn(x.x, v.x), 0.5f));
        v.y = __fadd_rn(v.y, __fmul_rn(__fsub_rn(x.y, v.y), 0.5f));
        v.z = __fadd_rn(v.z, __fmul_rn(__fsub_rn(x.z, v.z), 0.5f));
        v.w = __fadd_rn(v.w, __fmul_rn(__fsub_rn(x.w, v.w), 0.5f));
        const bool f0 = (v.x >= 0.5f), f1 = (v.y >= 0.5f);
        const bool f2 = (v.z >= 0.5f), f3 = (v.w >= 0.5f);
        IO[off] = make_float4(f0 ? 1.f : 0.f, f1 ? 1.f : 0.f,
                              f2 ? 1.f : 0.f, f3 ? 1.f : 0.f);
        v.x = f0 ? 0.f : v.x;
        v.y = f1 ? 0.f : v.y;
        v.z = f2 ? 0.f : v.z;
        v.w = f3 ? 0.f : v.w;
    }
}

// ================= launch =================
extern "C" void kernel_launch(void* const* d_in, const int* in_sizes, int n_in,
                              void* d_out, int out_size)
{
    (void)in_sizes; (void)n_in; (void)out_size;
    const float* x   = (const float*)d_in[0];
    const float* qw  = (const float*)d_in[1];
    const float* qb  = (const float*)d_in[2];
    const float* qg  = (const float*)d_in[3];
    const float* qbe = (const float*)d_in[4];
    const float* kw  = (const float*)d_in[5];
    const float* kb  = (const float*)d_in[6];
    const float* kg  = (const float*)d_in[7];
    const float* kbe = (const float*)d_in[8];
    const float* vw  = (const float*)d_in[9];
    const float* vb  = (const float*)d_in[10];
    const float* vg  = (const float*)d_in[11];
    const float* vbe = (const float*)d_in[12];
    const float* lw  = (const float*)d_in[13];
    const float* lb  = (const float*)d_in[14];
    const float* lg  = (const float*)d_in[15];
    const float* lbe = (const float*)d_in[16];

    float *Hq, *Hk, *Hv, *O, *Y;
    unsigned long long *Mq, *Mk, *Mv;
    unsigned *cnt;
    cudaGetSymbolAddress((void**)&Hq, g_Hq);
    cudaGetSymbolAddress((void**)&Hk, g_Hk);
    cudaGetSymbolAddress((void**)&Hv, g_Hv);
    cudaGetSymbolAddress((void**)&O,  g_O);
    cudaGetSymbolAddress((void**)&Y,  g_Y);
    cudaGetSymbolAddress((void**)&Mq, g_Mq);
    cudaGetSymbolAddress((void**)&Mk, g_Mk);
    cudaGetSymbolAddress((void**)&Mv, g_Mv);
    cudaGetSymbolAddress((void**)&cnt, g_cnt);

    // reset completion counters (graph node, per-replay deterministic)
    cudaMemsetAsync(cnt, 0, 256 * sizeof(unsigned));

    // Q/K/V projections + fused LN/LIF (masks only)
    gemm_ln_kernel<<<dim3(D_ / 128, N_ / 128, 3), 256>>>(
        x, qw, kw, vw, qb, kb, vb, Hq, Hk, Hv,
        qg, kg, vg, qbe, kbe, vbe,
        Mq, Mk, Mv,
        nullptr, nullptr, nullptr,
        cnt, 0, 1.0f);

    // attention per (h,t,b) — mask QK + mask-expanded dp4a AV (exact integers)
    attn_kernel<<<dim3(H_, T_, B_), 256>>>(Mq, Mk, Mv, O);

    // LIF (thr=0.5) over T, exact dyadic, in place -> binary
    lif2_kernel<<<(B_ * L_ * D_) / 1024, 256>>>((float4*)O);

    // final linear + fused LN/LIF -> d_out floats
    gemm_ln_kernel<<<dim3(D_ / 128, N_ / 128, 1), 256>>>(
        O, lw, lw, lw, lb, lb, lb, Y, Y, Y,
        lg, lg, lg, lbe, lbe, lbe,
        nullptr, nullptr, nullptr,
        (float*)d_out, (float*)d_out, (float*)d_out,
        cnt, 192, 1.0f);
}